// round 3
// baseline (speedup 1.0000x reference)
#include <cuda_runtime.h>
#include <math.h>

#define NN   20000
#define EMAX 320000
#define FDIM 512
#define NH   4
#define HC   128

// ---------------- scratch (static device globals; no allocation) ------------
__device__ float sc_g[(size_t)NN * FDIM];   // projected features g = h @ W
__device__ float sc_a[(size_t)NN * FDIM];   // ping buffer (h1)
__device__ float sc_b[(size_t)NN * FDIM];   // pong buffer (res0 / h2)
__device__ float sc_es[NN * NH];
__device__ float sc_ed[NN * NH];
__device__ int   sc_deg[NN];
__device__ int   sc_rowptr[NN + 1];
__device__ int   sc_cursor[NN];
__device__ int   sc_csr[EMAX + NN];
__device__ int   sc_is64;                   // 1 if edge_index is int64

// device-side buffer selection (host never touches symbol addresses)
__device__ __forceinline__ float* pick_rw(int sel, float* ext) {
    if (sel == 0) return ext;
    if (sel == 1) return sc_a;
    if (sel == 2) return sc_b;
    return sc_g;
}
__device__ __forceinline__ const float* pick_ro(int sel, const float* ext) {
    if (sel == 0) return ext;
    if (sel == 1) return sc_a;
    if (sel == 2) return sc_b;
    return sc_g;
}

__device__ __forceinline__ int load_edge(const void* ei, size_t idx) {
    if (sc_is64) return (int)((const long long*)ei)[idx];
    return ((const int*)ei)[idx];
}

// ---------------- dtype probe ------------------------------------------------
// If data is int64 with values < 2^31, every odd 32-bit word is 0.
// For int32 edge data, odd words are random node ids -> virtually never all 0.
__global__ void detect_k(const void* ei) {
    const int* p = (const int*)ei;
    int any = 0;
#pragma unroll 8
    for (int i = 0; i < 256; i++) any |= p[2 * i + 1];
    sc_is64 = (any == 0) ? 1 : 0;
}

// ---------------- CSR build -------------------------------------------------
__global__ void init_deg_k() {
    int i = blockIdx.x * blockDim.x + threadIdx.x;
    if (i < NN) sc_deg[i] = 1;   // self loop
}

__global__ void hist_k(const void* ei, int E) {
    int e = blockIdx.x * blockDim.x + threadIdx.x;
    if (e < E) {
        int d = load_edge(ei, (size_t)E + e);
        atomicAdd(&sc_deg[d], 1);
    }
}

// single-block exclusive scan over NN=20000 ints
__global__ void scan_k() {
    __shared__ int sums[1024];
    const int CH = 20;                       // 1024*20 = 20480 >= 20000
    int t = threadIdx.x;
    int base = t * CH;
    int local[CH];
    int s = 0;
#pragma unroll
    for (int i = 0; i < CH; i++) {
        int idx = base + i;
        int v = (idx < NN) ? sc_deg[idx] : 0;
        local[i] = s;
        s += v;
    }
    sums[t] = s;
    __syncthreads();
    for (int off = 1; off < 1024; off <<= 1) {
        int v = (t >= off) ? sums[t - off] : 0;
        __syncthreads();
        sums[t] += v;
        __syncthreads();
    }
    int offset = (t == 0) ? 0 : sums[t - 1];
#pragma unroll
    for (int i = 0; i < CH; i++) {
        int idx = base + i;
        if (idx < NN) {
            int r = offset + local[i];
            sc_rowptr[idx] = r;
            sc_cursor[idx] = r;
        }
    }
    if (t == 1023) sc_rowptr[NN] = sums[1023];
}

__global__ void scatter_k(const void* ei, int E) {
    int i = blockIdx.x * blockDim.x + threadIdx.x;
    if (i < E) {
        int d = load_edge(ei, (size_t)E + i);
        int s = load_edge(ei, i);
        int slot = atomicAdd(&sc_cursor[d], 1);
        sc_csr[slot] = s;
    } else if (i < E + NN) {
        int v = i - E;
        int slot = atomicAdd(&sc_cursor[v], 1);
        sc_csr[slot] = v;                     // self loop
    }
}

// ---------------- SGEMM: C[M,512] = A[M,K] @ B[K,512] -----------------------
#define BM 128
#define BN 128
#define BK 8
#define TM 8
#define TN 8

__global__ __launch_bounds__(256) void sgemm_k(const float* __restrict__ Aext,
                                               int asel,
                                               const float* __restrict__ B,
                                               int csel,
                                               int M, int K) {
    const float* A = pick_ro(asel, Aext);
    float* C = pick_rw(csel, nullptr);

    __shared__ float As[BK][BM];
    __shared__ float Bs[BK][BN];
    int tid = threadIdx.x;
    int bm = blockIdx.y * BM;
    int bn = blockIdx.x * BN;

    int arow = tid >> 1;             // 0..127
    int acol = (tid & 1) * 4;        // 0 or 4
    int brow = tid >> 5;             // 0..7
    int bcol = (tid & 31) * 4;       // 0..124
    int ty = tid >> 4;               // 0..15
    int tx = tid & 15;               // 0..15

    float acc[TM][TN];
#pragma unroll
    for (int i = 0; i < TM; i++)
#pragma unroll
        for (int j = 0; j < TN; j++) acc[i][j] = 0.f;

    bool arow_ok = (bm + arow) < M;
    const float* Aptr = A + (size_t)(bm + arow) * K + acol;
    const float* Bptr = B + (size_t)brow * FDIM + bn + bcol;

    for (int k0 = 0; k0 < K; k0 += BK) {
        float4 av = arow_ok ? *(const float4*)(Aptr + k0)
                            : make_float4(0.f, 0.f, 0.f, 0.f);
        As[acol + 0][arow] = av.x;
        As[acol + 1][arow] = av.y;
        As[acol + 2][arow] = av.z;
        As[acol + 3][arow] = av.w;
        *(float4*)&Bs[brow][bcol] = *(const float4*)(Bptr + (size_t)k0 * FDIM);
        __syncthreads();
#pragma unroll
        for (int kk = 0; kk < BK; kk++) {
            float a[TM], b[TN];
#pragma unroll
            for (int i = 0; i < TM; i++) a[i] = As[kk][ty * TM + i];
#pragma unroll
            for (int j = 0; j < TN; j++) b[j] = Bs[kk][tx * TN + j];
#pragma unroll
            for (int i = 0; i < TM; i++)
#pragma unroll
                for (int j = 0; j < TN; j++) acc[i][j] += a[i] * b[j];
        }
        __syncthreads();
    }

#pragma unroll
    for (int i = 0; i < TM; i++) {
        int r = bm + ty * TM + i;
        if (r < M) {
            float4 v0 = make_float4(acc[i][0], acc[i][1], acc[i][2], acc[i][3]);
            float4 v1 = make_float4(acc[i][4], acc[i][5], acc[i][6], acc[i][7]);
            float* cp = C + (size_t)r * FDIM + bn + tx * TN;
            *(float4*)cp = v0;
            *(float4*)(cp + 4) = v1;
        }
    }
}

// ---------------- attention scores e_s, e_d (reads sc_g) --------------------
__global__ __launch_bounds__(128) void scores_k(const float* __restrict__ asrc,
                                                const float* __restrict__ adst) {
    int node = blockIdx.x;
    int w = threadIdx.x >> 5, lane = threadIdx.x & 31;
    const float* gr = sc_g + (size_t)node * FDIM + w * HC;
    const float* as = asrc + w * HC;
    const float* ad = adst + w * HC;
    float s1 = 0.f, s2 = 0.f;
#pragma unroll
    for (int k = 0; k < 4; k++) {
        float v = gr[lane + 32 * k];
        s1 += v * as[lane + 32 * k];
        s2 += v * ad[lane + 32 * k];
    }
#pragma unroll
    for (int o = 16; o; o >>= 1) {
        s1 += __shfl_down_sync(0xffffffffu, s1, o);
        s2 += __shfl_down_sync(0xffffffffu, s2, o);
    }
    if (lane == 0) {
        sc_es[node * NH + w] = s1;
        sc_ed[node * NH + w] = s2;
    }
}

// ---------------- fused segment softmax + aggregate + bias + res + relu -----
__global__ __launch_bounds__(128) void agg_k(const float* __restrict__ bias,
                                             int rsel,
                                             float* __restrict__ outext,
                                             int osel) {
    const float* res = pick_ro(rsel, nullptr);
    float* out = pick_rw(osel, outext);
    const float* g = sc_g;

    int d = blockIdx.x;
    int w = threadIdx.x >> 5, lane = threadIdx.x & 31;
    int beg = sc_rowptr[d], end = sc_rowptr[d + 1];
    float edv = sc_ed[d * NH + w];

    // pass 1: per-head max over in-edges (lane-strided)
    float m = -INFINITY;
    for (int j = beg + lane; j < end; j += 32) {
        int s = sc_csr[j];
        float e = sc_es[s * NH + w] + edv;
        e = e > 0.f ? e : 0.2f * e;
        m = fmaxf(m, e);
    }
#pragma unroll
    for (int o = 16; o; o >>= 1) m = fmaxf(m, __shfl_xor_sync(0xffffffffu, m, o));

    // pass 2: denom
    float den = 0.f;
    for (int j = beg + lane; j < end; j += 32) {
        int s = sc_csr[j];
        float e = sc_es[s * NH + w] + edv;
        e = e > 0.f ? e : 0.2f * e;
        den += __expf(e - m);
    }
#pragma unroll
    for (int o = 16; o; o >>= 1) den += __shfl_xor_sync(0xffffffffu, den, o);
    float inv = 1.f / (den + 1e-16f);

    // pass 3: weighted gather-accumulate (all lanes, sequential over edges)
    float4 acc = make_float4(0.f, 0.f, 0.f, 0.f);
    const float* gh = g + w * HC + 4 * lane;
#pragma unroll 4
    for (int j = beg; j < end; j++) {
        int s = sc_csr[j];                       // broadcast
        float e = sc_es[s * NH + w] + edv;       // broadcast within warp
        e = e > 0.f ? e : 0.2f * e;
        float wt = __expf(e - m) * inv;
        float4 gv = *(const float4*)(gh + (size_t)s * FDIM);
        acc.x += wt * gv.x;
        acc.y += wt * gv.y;
        acc.z += wt * gv.z;
        acc.w += wt * gv.w;
    }

    int c = w * HC + 4 * lane;
    float4 bv = *(const float4*)(bias + c);
    float4 rv = *(const float4*)(res + (size_t)d * FDIM + c);
    float4 o;
    o.x = fmaxf(acc.x + bv.x + rv.x, 0.f);
    o.y = fmaxf(acc.y + bv.y + rv.y, 0.f);
    o.z = fmaxf(acc.z + bv.z + rv.z, 0.f);
    o.w = fmaxf(acc.w + bv.w + rv.w, 0.f);
    *(float4*)(out + (size_t)d * FDIM + c) = o;
}

// ---------------- host orchestration ----------------------------------------
extern "C" void kernel_launch(void* const* d_in, const int* in_sizes, int n_in,
                              void* d_out, int out_size) {
    const float* x       = (const float*)d_in[0];
    const void* ei       = d_in[1];
    const float* w0      = (const float*)d_in[2];
    const float* b0      = (const float*)d_in[3];
    const float* asrc0   = (const float*)d_in[4];
    const float* adst0   = (const float*)d_in[5];
    const float* res_w0  = (const float*)d_in[6];
    const float* w1      = (const float*)d_in[7];
    const float* b1      = (const float*)d_in[8];
    const float* asrc1   = (const float*)d_in[9];
    const float* adst1   = (const float*)d_in[10];
    const float* w2      = (const float*)d_in[11];
    const float* b2      = (const float*)d_in[12];
    const float* asrc2   = (const float*)d_in[13];
    const float* adst2   = (const float*)d_in[14];
    float* out           = (float*)d_out;

    int E = in_sizes[1] / 2;

    // CSR by dst (shared across all 3 layers)
    detect_k<<<1, 1>>>(ei);
    init_deg_k<<<(NN + 255) / 256, 256>>>();
    hist_k<<<(E + 255) / 256, 256>>>(ei, E);
    scan_k<<<1, 1024>>>();
    scatter_k<<<(E + NN + 255) / 256, 256>>>(ei, E);

    dim3 ggrid(FDIM / BN, (NN + BM - 1) / BM);

    // selectors: 0 = external ptr, 1 = sc_a, 2 = sc_b, 3 = sc_g
    // layer 0 (in=256): g = x@w0 -> sc_g ; res = x@res_w0 -> sc_b
    sgemm_k<<<ggrid, 256>>>(x, 0, w0, 3, NN, 256);
    sgemm_k<<<ggrid, 256>>>(x, 0, res_w0, 2, NN, 256);
    scores_k<<<NN, 128>>>(asrc0, adst0);
    agg_k<<<NN, 128>>>(b0, /*res=*/2, nullptr, /*out=*/1);   // h1 -> sc_a

    // layer 1 (identity residual): g = h1@w1 -> sc_g
    sgemm_k<<<ggrid, 256>>>(nullptr, 1, w1, 3, NN, 512);
    scores_k<<<NN, 128>>>(asrc1, adst1);
    agg_k<<<NN, 128>>>(b1, /*res=*/1, nullptr, /*out=*/2);   // h2 -> sc_b

    // layer 2 (identity residual): g = h2@w2 -> sc_g ; output -> d_out
    sgemm_k<<<ggrid, 256>>>(nullptr, 2, w2, 3, NN, 512);
    scores_k<<<NN, 128>>>(asrc2, adst2);
    agg_k<<<NN, 128>>>(b2, /*res=*/2, out, /*out=*/0);
}

// round 5
// speedup vs baseline: 2.0805x; 2.0805x over previous
#include <cuda_runtime.h>
#include <math.h>

#define NN   20000
#define EMAX 320000
#define FDIM 512
#define NH   4
#define HC   128

// ---------------- scratch (static device globals; no allocation) ------------
__device__ float sc_g[(size_t)NN * FDIM];   // projected features g = h @ W
__device__ float sc_a[(size_t)NN * FDIM];   // ping buffer (h1)
__device__ float sc_b[(size_t)NN * FDIM];   // pong buffer (res0 / h2)
__device__ float sc_es[NN * NH];
__device__ float sc_ed[NN * NH];
__device__ int   sc_deg[NN];
__device__ int   sc_rowptr[NN + 1];
__device__ int   sc_cursor[NN];
__device__ int   sc_csr[EMAX + NN];
__device__ int   sc_is64;                   // 1 if edge_index is int64

// device-side buffer selection (host never touches symbol addresses)
__device__ __forceinline__ float* pick_rw(int sel, float* ext) {
    if (sel == 0) return ext;
    if (sel == 1) return sc_a;
    if (sel == 2) return sc_b;
    return sc_g;
}
__device__ __forceinline__ const float* pick_ro(int sel, const float* ext) {
    if (sel == 0) return ext;
    if (sel == 1) return sc_a;
    if (sel == 2) return sc_b;
    return sc_g;
}

__device__ __forceinline__ int load_edge(const void* ei, size_t idx) {
    if (sc_is64) return (int)((const long long*)ei)[idx];
    return ((const int*)ei)[idx];
}

// ---------------- dtype probe ------------------------------------------------
__global__ void detect_k(const void* ei) {
    const int* p = (const int*)ei;
    int any = 0;
#pragma unroll 8
    for (int i = 0; i < 256; i++) any |= p[2 * i + 1];
    sc_is64 = (any == 0) ? 1 : 0;
}

// ---------------- CSR build -------------------------------------------------
__global__ void init_deg_k() {
    int i = blockIdx.x * blockDim.x + threadIdx.x;
    if (i < NN) sc_deg[i] = 1;   // self loop
}

__global__ void hist_k(const void* ei, int E) {
    int e = blockIdx.x * blockDim.x + threadIdx.x;
    if (e < E) {
        int d = load_edge(ei, (size_t)E + e);
        atomicAdd(&sc_deg[d], 1);
    }
}

// single-block exclusive scan over NN=20000 ints
__global__ void scan_k() {
    __shared__ int sums[1024];
    const int CH = 20;
    int t = threadIdx.x;
    int base = t * CH;
    int local[CH];
    int s = 0;
#pragma unroll
    for (int i = 0; i < CH; i++) {
        int idx = base + i;
        int v = (idx < NN) ? sc_deg[idx] : 0;
        local[i] = s;
        s += v;
    }
    sums[t] = s;
    __syncthreads();
    for (int off = 1; off < 1024; off <<= 1) {
        int v = (t >= off) ? sums[t - off] : 0;
        __syncthreads();
        sums[t] += v;
        __syncthreads();
    }
    int offset = (t == 0) ? 0 : sums[t - 1];
#pragma unroll
    for (int i = 0; i < CH; i++) {
        int idx = base + i;
        if (idx < NN) {
            int r = offset + local[i];
            sc_rowptr[idx] = r;
            sc_cursor[idx] = r;
        }
    }
    if (t == 1023) sc_rowptr[NN] = sums[1023];
}

__global__ void scatter_k(const void* ei, int E) {
    int i = blockIdx.x * blockDim.x + threadIdx.x;
    if (i < E) {
        int d = load_edge(ei, (size_t)E + i);
        int s = load_edge(ei, i);
        int slot = atomicAdd(&sc_cursor[d], 1);
        sc_csr[slot] = s;
    } else if (i < E + NN) {
        int v = i - E;
        int slot = atomicAdd(&sc_cursor[v], 1);
        sc_csr[slot] = v;                     // self loop
    }
}

// ---------------- TF32 tensor-core GEMM: C[M,512] = A[M,K] @ B[K,512] -------
// Tile 128x128x32, 256 threads, 8 warps each computing 64x32 via m16n8k8.
#define GBM 128
#define GBN 128
#define GBK 32
#define AS_LD 36
#define BS_LD 136

__device__ __forceinline__ float to_tf32(float x) {
    unsigned y;
    asm("cvt.rna.tf32.f32 %0, %1;" : "=r"(y) : "f"(x));
    return __uint_as_float(y);
}

__device__ __forceinline__ void mma_tf32(float* d, const float* a, const float* b) {
    unsigned const* A = (unsigned const*)a;
    unsigned const* B = (unsigned const*)b;
    asm volatile(
        "mma.sync.aligned.m16n8k8.row.col.f32.tf32.tf32.f32 "
        "{%0,%1,%2,%3}, {%4,%5,%6,%7}, {%8,%9}, {%0,%1,%2,%3};"
        : "+f"(d[0]), "+f"(d[1]), "+f"(d[2]), "+f"(d[3])
        : "r"(A[0]), "r"(A[1]), "r"(A[2]), "r"(A[3]), "r"(B[0]), "r"(B[1]));
}

__global__ __launch_bounds__(256, 1) void tgemm_k(const float* __restrict__ Aext,
                                                  int asel,
                                                  const float* __restrict__ B,
                                                  int csel,
                                                  int M, int K) {
    const float* A = pick_ro(asel, Aext);
    float* C = pick_rw(csel, nullptr);

    __shared__ float As[GBM][AS_LD];   // [m][k], pad 4
    __shared__ float Bs[GBK][BS_LD];   // [k][n], pad 8

    int tid  = threadIdx.x;
    int lane = tid & 31;
    int warp = tid >> 5;
    int wm = (warp >> 2) * 64;          // 0 or 64
    int wn = (warp & 3) * 32;           // 0,32,64,96
    int bm = blockIdx.y * GBM;
    int bn = blockIdx.x * GBN;

    // global load mapping
    int aRow = tid >> 3;                // 0..31 (row within 32-row slab)
    int aCol = (tid & 7) * 4;           // 0..28
    int bRow = tid >> 5;                // 0..7
    int bCol = (tid & 31) * 4;          // 0..124

    float acc[4][4][4];
#pragma unroll
    for (int i = 0; i < 4; i++)
#pragma unroll
        for (int j = 0; j < 4; j++)
#pragma unroll
            for (int q = 0; q < 4; q++) acc[i][j][q] = 0.f;

    float4 ra[4], rb[4];
    int nk = K / GBK;

    // ---- load tile 0 ----
#pragma unroll
    for (int i = 0; i < 4; i++) {
        int r = aRow + 32 * i;
        ra[i] = (bm + r < M) ? *(const float4*)(A + (size_t)(bm + r) * K + aCol)
                             : make_float4(0.f, 0.f, 0.f, 0.f);
        rb[i] = *(const float4*)(B + (size_t)(bRow + 8 * i) * FDIM + bn + bCol);
    }

    for (int kt = 0; kt < nk; kt++) {
        // store current regs -> smem (with tf32 rounding)
#pragma unroll
        for (int i = 0; i < 4; i++) {
            int m = aRow + 32 * i;
            As[m][aCol + 0] = to_tf32(ra[i].x);
            As[m][aCol + 1] = to_tf32(ra[i].y);
            As[m][aCol + 2] = to_tf32(ra[i].z);
            As[m][aCol + 3] = to_tf32(ra[i].w);
            float4 v = rb[i];
            v.x = to_tf32(v.x); v.y = to_tf32(v.y);
            v.z = to_tf32(v.z); v.w = to_tf32(v.w);
            *(float4*)&Bs[bRow + 8 * i][bCol] = v;
        }
        __syncthreads();

        // prefetch next tile into regs
        if (kt + 1 < nk) {
            int kb = (kt + 1) * GBK;
#pragma unroll
            for (int i = 0; i < 4; i++) {
                int r = aRow + 32 * i;
                ra[i] = (bm + r < M)
                      ? *(const float4*)(A + (size_t)(bm + r) * K + kb + aCol)
                      : make_float4(0.f, 0.f, 0.f, 0.f);
                rb[i] = *(const float4*)(B + (size_t)(kb + bRow + 8 * i) * FDIM + bn + bCol);
            }
        }

        // compute on smem tile
#pragma unroll
        for (int ks = 0; ks < 4; ks++) {
            int k0 = ks * 8;
            float afr[4][4], bfr[4][2];
#pragma unroll
            for (int mt = 0; mt < 4; mt++) {
                int m = wm + mt * 16 + (lane >> 2);
                int k = k0 + (lane & 3);
                afr[mt][0] = As[m][k];
                afr[mt][1] = As[m + 8][k];
                afr[mt][2] = As[m][k + 4];
                afr[mt][3] = As[m + 8][k + 4];
            }
#pragma unroll
            for (int nt = 0; nt < 4; nt++) {
                int n = wn + nt * 8 + (lane >> 2);
                int k = k0 + (lane & 3);
                bfr[nt][0] = Bs[k][n];
                bfr[nt][1] = Bs[k + 4][n];
            }
#pragma unroll
            for (int mt = 0; mt < 4; mt++)
#pragma unroll
                for (int nt = 0; nt < 4; nt++)
                    mma_tf32(acc[mt][nt], afr[mt], bfr[nt]);
        }
        __syncthreads();
    }

    // ---- epilogue ----
#pragma unroll
    for (int mt = 0; mt < 4; mt++) {
#pragma unroll
        for (int nt = 0; nt < 4; nt++) {
            int r = bm + wm + mt * 16 + (lane >> 2);
            int c = bn + wn + nt * 8 + (lane & 3) * 2;
            if (r < M) {
                float2 v = make_float2(acc[mt][nt][0], acc[mt][nt][1]);
                *(float2*)(C + (size_t)r * FDIM + c) = v;
            }
            if (r + 8 < M) {
                float2 v = make_float2(acc[mt][nt][2], acc[mt][nt][3]);
                *(float2*)(C + (size_t)(r + 8) * FDIM + c) = v;
            }
        }
    }
}

// ---------------- attention scores e_s, e_d (reads sc_g) --------------------
__global__ __launch_bounds__(128) void scores_k(const float* __restrict__ asrc,
                                                const float* __restrict__ adst) {
    int node = blockIdx.x;
    int w = threadIdx.x >> 5, lane = threadIdx.x & 31;
    const float* gr = sc_g + (size_t)node * FDIM + w * HC;
    const float* as = asrc + w * HC;
    const float* ad = adst + w * HC;
    float s1 = 0.f, s2 = 0.f;
#pragma unroll
    for (int k = 0; k < 4; k++) {
        float v = gr[lane + 32 * k];
        s1 += v * as[lane + 32 * k];
        s2 += v * ad[lane + 32 * k];
    }
#pragma unroll
    for (int o = 16; o; o >>= 1) {
        s1 += __shfl_down_sync(0xffffffffu, s1, o);
        s2 += __shfl_down_sync(0xffffffffu, s2, o);
    }
    if (lane == 0) {
        sc_es[node * NH + w] = s1;
        sc_ed[node * NH + w] = s2;
    }
}

// ---------------- fused segment softmax + aggregate + bias + res + relu -----
__global__ __launch_bounds__(128) void agg_k(const float* __restrict__ bias,
                                             int rsel,
                                             float* __restrict__ outext,
                                             int osel) {
    const float* res = pick_ro(rsel, nullptr);
    float* out = pick_rw(osel, outext);
    const float* g = sc_g;

    int d = blockIdx.x;
    int w = threadIdx.x >> 5, lane = threadIdx.x & 31;
    int beg = sc_rowptr[d], end = sc_rowptr[d + 1];
    float edv = sc_ed[d * NH + w];

    float m = -INFINITY;
    for (int j = beg + lane; j < end; j += 32) {
        int s = sc_csr[j];
        float e = sc_es[s * NH + w] + edv;
        e = e > 0.f ? e : 0.2f * e;
        m = fmaxf(m, e);
    }
#pragma unroll
    for (int o = 16; o; o >>= 1) m = fmaxf(m, __shfl_xor_sync(0xffffffffu, m, o));

    float den = 0.f;
    for (int j = beg + lane; j < end; j += 32) {
        int s = sc_csr[j];
        float e = sc_es[s * NH + w] + edv;
        e = e > 0.f ? e : 0.2f * e;
        den += __expf(e - m);
    }
#pragma unroll
    for (int o = 16; o; o >>= 1) den += __shfl_xor_sync(0xffffffffu, den, o);
    float inv = 1.f / (den + 1e-16f);

    float4 acc = make_float4(0.f, 0.f, 0.f, 0.f);
    const float* gh = g + w * HC + 4 * lane;
#pragma unroll 4
    for (int j = beg; j < end; j++) {
        int s = sc_csr[j];
        float e = sc_es[s * NH + w] + edv;
        e = e > 0.f ? e : 0.2f * e;
        float wt = __expf(e - m) * inv;
        float4 gv = *(const float4*)(gh + (size_t)s * FDIM);
        acc.x += wt * gv.x;
        acc.y += wt * gv.y;
        acc.z += wt * gv.z;
        acc.w += wt * gv.w;
    }

    int c = w * HC + 4 * lane;
    float4 bv = *(const float4*)(bias + c);
    float4 rv = *(const float4*)(res + (size_t)d * FDIM + c);
    float4 o;
    o.x = fmaxf(acc.x + bv.x + rv.x, 0.f);
    o.y = fmaxf(acc.y + bv.y + rv.y, 0.f);
    o.z = fmaxf(acc.z + bv.z + rv.z, 0.f);
    o.w = fmaxf(acc.w + bv.w + rv.w, 0.f);
    *(float4*)(out + (size_t)d * FDIM + c) = o;
}

// ---------------- host orchestration ----------------------------------------
extern "C" void kernel_launch(void* const* d_in, const int* in_sizes, int n_in,
                              void* d_out, int out_size) {
    const float* x       = (const float*)d_in[0];
    const void* ei       = d_in[1];
    const float* w0      = (const float*)d_in[2];
    const float* b0      = (const float*)d_in[3];
    const float* asrc0   = (const float*)d_in[4];
    const float* adst0   = (const float*)d_in[5];
    const float* res_w0  = (const float*)d_in[6];
    const float* w1      = (const float*)d_in[7];
    const float* b1      = (const float*)d_in[8];
    const float* asrc1   = (const float*)d_in[9];
    const float* adst1   = (const float*)d_in[10];
    const float* w2      = (const float*)d_in[11];
    const float* b2      = (const float*)d_in[12];
    const float* asrc2   = (const float*)d_in[13];
    const float* adst2   = (const float*)d_in[14];
    float* out           = (float*)d_out;

    int E = in_sizes[1] / 2;

    detect_k<<<1, 1>>>(ei);
    init_deg_k<<<(NN + 255) / 256, 256>>>();
    hist_k<<<(E + 255) / 256, 256>>>(ei, E);
    scan_k<<<1, 1024>>>();
    scatter_k<<<(E + NN + 255) / 256, 256>>>(ei, E);

    dim3 ggrid(FDIM / GBN, (NN + GBM - 1) / GBM);

    // selectors: 0 = external ptr, 1 = sc_a, 2 = sc_b, 3 = sc_g
    tgemm_k<<<ggrid, 256>>>(x, 0, w0, 3, NN, 256);
    tgemm_k<<<ggrid, 256>>>(x, 0, res_w0, 2, NN, 256);
    scores_k<<<NN, 128>>>(asrc0, adst0);
    agg_k<<<NN, 128>>>(b0, /*res=*/2, nullptr, /*out=*/1);   // h1 -> sc_a

    tgemm_k<<<ggrid, 256>>>(nullptr, 1, w1, 3, NN, 512);
    scores_k<<<NN, 128>>>(asrc1, adst1);
    agg_k<<<NN, 128>>>(b1, /*res=*/1, nullptr, /*out=*/2);   // h2 -> sc_b

    tgemm_k<<<ggrid, 256>>>(nullptr, 2, w2, 3, NN, 512);
    scores_k<<<NN, 128>>>(asrc2, adst2);
    agg_k<<<NN, 128>>>(b2, /*res=*/2, out, /*out=*/0);
}

// round 6
// speedup vs baseline: 2.2213x; 1.0677x over previous
#include <cuda_runtime.h>
#include <math.h>

#define NN   20000
#define EMAX 320000
#define FDIM 512
#define NH   4
#define HC   128
#define DCAP 256

// ---------------- scratch (static device globals; no allocation) ------------
__device__ float sc_g[(size_t)NN * FDIM];   // projected features g = h @ W
__device__ float sc_a[(size_t)NN * FDIM];   // ping buffer (h1)
__device__ float sc_b[(size_t)NN * FDIM];   // pong buffer (res0 / h2)
__device__ float sc_es[NN * NH];
__device__ float sc_ed[NN * NH];
__device__ int   sc_deg[NN];
__device__ int   sc_rowptr[NN + 1];
__device__ int   sc_cursor[NN];
__device__ int   sc_csr[EMAX + NN];
__device__ int   sc_is64;                   // 1 if edge_index is int64

// device-side buffer selection (host never touches symbol addresses)
__device__ __forceinline__ float* pick_rw(int sel, float* ext) {
    if (sel == 0) return ext;
    if (sel == 1) return sc_a;
    if (sel == 2) return sc_b;
    return sc_g;
}
__device__ __forceinline__ const float* pick_ro(int sel, const float* ext) {
    if (sel == 0) return ext;
    if (sel == 1) return sc_a;
    if (sel == 2) return sc_b;
    return sc_g;
}

__device__ __forceinline__ int load_edge(const void* ei, size_t idx) {
    if (sc_is64) return (int)((const long long*)ei)[idx];
    return ((const int*)ei)[idx];
}

// ---------------- dtype probe ------------------------------------------------
__global__ void detect_k(const void* ei) {
    const int* p = (const int*)ei;
    int any = 0;
#pragma unroll 8
    for (int i = 0; i < 256; i++) any |= p[2 * i + 1];
    sc_is64 = (any == 0) ? 1 : 0;
}

// ---------------- CSR build -------------------------------------------------
__global__ void init_deg_k() {
    int i = blockIdx.x * blockDim.x + threadIdx.x;
    if (i < NN) sc_deg[i] = 1;   // self loop
}

__global__ void hist_k(const void* ei, int E) {
    int e = blockIdx.x * blockDim.x + threadIdx.x;
    if (e < E) {
        int d = load_edge(ei, (size_t)E + e);
        atomicAdd(&sc_deg[d], 1);
    }
}

// single-block exclusive scan over NN=20000 ints
__global__ void scan_k() {
    __shared__ int sums[1024];
    const int CH = 20;
    int t = threadIdx.x;
    int base = t * CH;
    int local[CH];
    int s = 0;
#pragma unroll
    for (int i = 0; i < CH; i++) {
        int idx = base + i;
        int v = (idx < NN) ? sc_deg[idx] : 0;
        local[i] = s;
        s += v;
    }
    sums[t] = s;
    __syncthreads();
    for (int off = 1; off < 1024; off <<= 1) {
        int v = (t >= off) ? sums[t - off] : 0;
        __syncthreads();
        sums[t] += v;
        __syncthreads();
    }
    int offset = (t == 0) ? 0 : sums[t - 1];
#pragma unroll
    for (int i = 0; i < CH; i++) {
        int idx = base + i;
        if (idx < NN) {
            int r = offset + local[i];
            sc_rowptr[idx] = r;
            sc_cursor[idx] = r;
        }
    }
    if (t == 1023) sc_rowptr[NN] = sums[1023];
}

__global__ void scatter_k(const void* ei, int E) {
    int i = blockIdx.x * blockDim.x + threadIdx.x;
    if (i < E) {
        int d = load_edge(ei, (size_t)E + i);
        int s = load_edge(ei, i);
        int slot = atomicAdd(&sc_cursor[d], 1);
        sc_csr[slot] = s;
    } else if (i < E + NN) {
        int v = i - E;
        int slot = atomicAdd(&sc_cursor[v], 1);
        sc_csr[slot] = v;                     // self loop
    }
}

// ---------------- TF32 tensor-core GEMM: C[M,512] = A[M,K] @ B[K,512] -------
#define GBM 128
#define GBN 128
#define GBK 32
#define AS_LD 36
#define BS_LD 136

__device__ __forceinline__ float to_tf32(float x) {
    unsigned y;
    asm("cvt.rna.tf32.f32 %0, %1;" : "=r"(y) : "f"(x));
    return __uint_as_float(y);
}

__device__ __forceinline__ void mma_tf32(float* d, const float* a, const float* b) {
    unsigned const* A = (unsigned const*)a;
    unsigned const* B = (unsigned const*)b;
    asm volatile(
        "mma.sync.aligned.m16n8k8.row.col.f32.tf32.tf32.f32 "
        "{%0,%1,%2,%3}, {%4,%5,%6,%7}, {%8,%9}, {%0,%1,%2,%3};"
        : "+f"(d[0]), "+f"(d[1]), "+f"(d[2]), "+f"(d[3])
        : "r"(A[0]), "r"(A[1]), "r"(A[2]), "r"(A[3]), "r"(B[0]), "r"(B[1]));
}

__global__ __launch_bounds__(256, 1) void tgemm_k(const float* __restrict__ Aext,
                                                  int asel,
                                                  const float* __restrict__ B,
                                                  int csel,
                                                  int M, int K) {
    const float* A = pick_ro(asel, Aext);
    float* C = pick_rw(csel, nullptr);

    __shared__ float As[GBM][AS_LD];   // [m][k], pad 4
    __shared__ float Bs[GBK][BS_LD];   // [k][n], pad 8

    int tid  = threadIdx.x;
    int lane = tid & 31;
    int warp = tid >> 5;
    int wm = (warp >> 2) * 64;
    int wn = (warp & 3) * 32;
    int bm = blockIdx.y * GBM;
    int bn = blockIdx.x * GBN;

    int aRow = tid >> 3;
    int aCol = (tid & 7) * 4;
    int bRow = tid >> 5;
    int bCol = (tid & 31) * 4;

    float acc[4][4][4];
#pragma unroll
    for (int i = 0; i < 4; i++)
#pragma unroll
        for (int j = 0; j < 4; j++)
#pragma unroll
            for (int q = 0; q < 4; q++) acc[i][j][q] = 0.f;

    float4 ra[4], rb[4];
    int nk = K / GBK;

#pragma unroll
    for (int i = 0; i < 4; i++) {
        int r = aRow + 32 * i;
        ra[i] = (bm + r < M) ? *(const float4*)(A + (size_t)(bm + r) * K + aCol)
                             : make_float4(0.f, 0.f, 0.f, 0.f);
        rb[i] = *(const float4*)(B + (size_t)(bRow + 8 * i) * FDIM + bn + bCol);
    }

    for (int kt = 0; kt < nk; kt++) {
#pragma unroll
        for (int i = 0; i < 4; i++) {
            int m = aRow + 32 * i;
            As[m][aCol + 0] = to_tf32(ra[i].x);
            As[m][aCol + 1] = to_tf32(ra[i].y);
            As[m][aCol + 2] = to_tf32(ra[i].z);
            As[m][aCol + 3] = to_tf32(ra[i].w);
            float4 v = rb[i];
            v.x = to_tf32(v.x); v.y = to_tf32(v.y);
            v.z = to_tf32(v.z); v.w = to_tf32(v.w);
            *(float4*)&Bs[bRow + 8 * i][bCol] = v;
        }
        __syncthreads();

        if (kt + 1 < nk) {
            int kb = (kt + 1) * GBK;
#pragma unroll
            for (int i = 0; i < 4; i++) {
                int r = aRow + 32 * i;
                ra[i] = (bm + r < M)
                      ? *(const float4*)(A + (size_t)(bm + r) * K + kb + aCol)
                      : make_float4(0.f, 0.f, 0.f, 0.f);
                rb[i] = *(const float4*)(B + (size_t)(kb + bRow + 8 * i) * FDIM + bn + bCol);
            }
        }

#pragma unroll
        for (int ks = 0; ks < 4; ks++) {
            int k0 = ks * 8;
            float afr[4][4], bfr[4][2];
#pragma unroll
            for (int mt = 0; mt < 4; mt++) {
                int m = wm + mt * 16 + (lane >> 2);
                int k = k0 + (lane & 3);
                afr[mt][0] = As[m][k];
                afr[mt][1] = As[m + 8][k];
                afr[mt][2] = As[m][k + 4];
                afr[mt][3] = As[m + 8][k + 4];
            }
#pragma unroll
            for (int nt = 0; nt < 4; nt++) {
                int n = wn + nt * 8 + (lane >> 2);
                int k = k0 + (lane & 3);
                bfr[nt][0] = Bs[k][n];
                bfr[nt][1] = Bs[k + 4][n];
            }
#pragma unroll
            for (int mt = 0; mt < 4; mt++)
#pragma unroll
                for (int nt = 0; nt < 4; nt++)
                    mma_tf32(acc[mt][nt], afr[mt], bfr[nt]);
        }
        __syncthreads();
    }

#pragma unroll
    for (int mt = 0; mt < 4; mt++) {
#pragma unroll
        for (int nt = 0; nt < 4; nt++) {
            int r = bm + wm + mt * 16 + (lane >> 2);
            int c = bn + wn + nt * 8 + (lane & 3) * 2;
            if (r < M) {
                float2 v = make_float2(acc[mt][nt][0], acc[mt][nt][1]);
                *(float2*)(C + (size_t)r * FDIM + c) = v;
            }
            if (r + 8 < M) {
                float2 v = make_float2(acc[mt][nt][2], acc[mt][nt][3]);
                *(float2*)(C + (size_t)(r + 8) * FDIM + c) = v;
            }
        }
    }
}

// ---------------- attention scores e_s, e_d (reads sc_g) --------------------
__global__ __launch_bounds__(128) void scores_k(const float* __restrict__ asrc,
                                                const float* __restrict__ adst) {
    int node = blockIdx.x;
    int w = threadIdx.x >> 5, lane = threadIdx.x & 31;
    const float* gr = sc_g + (size_t)node * FDIM + w * HC;
    const float* as = asrc + w * HC;
    const float* ad = adst + w * HC;
    float s1 = 0.f, s2 = 0.f;
#pragma unroll
    for (int k = 0; k < 4; k++) {
        float v = gr[lane + 32 * k];
        s1 += v * as[lane + 32 * k];
        s2 += v * ad[lane + 32 * k];
    }
#pragma unroll
    for (int o = 16; o; o >>= 1) {
        s1 += __shfl_down_sync(0xffffffffu, s1, o);
        s2 += __shfl_down_sync(0xffffffffu, s2, o);
    }
    if (lane == 0) {
        sc_es[node * NH + w] = s1;
        sc_ed[node * NH + w] = s2;
    }
}

// ---------------- fused segment softmax + aggregate + bias + res + relu -----
__global__ __launch_bounds__(128) void agg_k(const float* __restrict__ bias,
                                             int rsel,
                                             float* __restrict__ outext,
                                             int osel) {
    const float* res = pick_ro(rsel, nullptr);
    float* out = pick_rw(osel, outext);

    __shared__ float w_sh[NH][DCAP];
    __shared__ int   idx_sh[DCAP];

    int d = blockIdx.x;
    int w = threadIdx.x >> 5, lane = threadIdx.x & 31;
    int beg = sc_rowptr[d], end = sc_rowptr[d + 1];
    int deg = end - beg;
    float edv = sc_ed[d * NH + w];

    float4 acc = make_float4(0.f, 0.f, 0.f, 0.f);
    const float* gh = sc_g + w * HC + 4 * lane;

    if (deg <= DCAP) {
        // pass 1: compute leaky scores into smem (+stage indices), track max
        float m = -INFINITY;
        for (int j = lane; j < deg; j += 32) {
            int s = sc_csr[beg + j];
            if (w == 0) idx_sh[j] = s;
            float e = sc_es[s * NH + w] + edv;
            e = e > 0.f ? e : 0.2f * e;
            w_sh[w][j] = e;
            m = fmaxf(m, e);
        }
#pragma unroll
        for (int o = 16; o; o >>= 1) m = fmaxf(m, __shfl_xor_sync(0xffffffffu, m, o));

        // pass 2: exponentiate in place, accumulate denom
        float den = 0.f;
        for (int j = lane; j < deg; j += 32) {
            float ex = __expf(w_sh[w][j] - m);
            w_sh[w][j] = ex;
            den += ex;
        }
#pragma unroll
        for (int o = 16; o; o >>= 1) den += __shfl_xor_sync(0xffffffffu, den, o);
        float inv = 1.f / (den + 1e-16f);

        __syncthreads();   // idx_sh (warp0) + w_sh visible

        // pass 3: pure gather-FMA with smem weights
#pragma unroll 4
        for (int j = 0; j < deg; j++) {
            int s = idx_sh[j];
            float wt = w_sh[w][j] * inv;
            float4 gv = *(const float4*)(gh + (size_t)s * FDIM);
            acc.x += wt * gv.x;
            acc.y += wt * gv.y;
            acc.z += wt * gv.z;
            acc.w += wt * gv.w;
        }
    } else {
        // fallback: recompute path (never expected for this graph, kept for safety)
        float m = -INFINITY;
        for (int j = beg + lane; j < end; j += 32) {
            int s = sc_csr[j];
            float e = sc_es[s * NH + w] + edv;
            e = e > 0.f ? e : 0.2f * e;
            m = fmaxf(m, e);
        }
#pragma unroll
        for (int o = 16; o; o >>= 1) m = fmaxf(m, __shfl_xor_sync(0xffffffffu, m, o));
        float den = 0.f;
        for (int j = beg + lane; j < end; j += 32) {
            int s = sc_csr[j];
            float e = sc_es[s * NH + w] + edv;
            e = e > 0.f ? e : 0.2f * e;
            den += __expf(e - m);
        }
#pragma unroll
        for (int o = 16; o; o >>= 1) den += __shfl_xor_sync(0xffffffffu, den, o);
        float inv = 1.f / (den + 1e-16f);
#pragma unroll 4
        for (int j = beg; j < end; j++) {
            int s = sc_csr[j];
            float e = sc_es[s * NH + w] + edv;
            e = e > 0.f ? e : 0.2f * e;
            float wt = __expf(e - m) * inv;
            float4 gv = *(const float4*)(gh + (size_t)s * FDIM);
            acc.x += wt * gv.x;
            acc.y += wt * gv.y;
            acc.z += wt * gv.z;
            acc.w += wt * gv.w;
        }
    }

    int c = w * HC + 4 * lane;
    float4 bv = *(const float4*)(bias + c);
    float4 rv = *(const float4*)(res + (size_t)d * FDIM + c);
    float4 o;
    o.x = fmaxf(acc.x + bv.x + rv.x, 0.f);
    o.y = fmaxf(acc.y + bv.y + rv.y, 0.f);
    o.z = fmaxf(acc.z + bv.z + rv.z, 0.f);
    o.w = fmaxf(acc.w + bv.w + rv.w, 0.f);
    *(float4*)(out + (size_t)d * FDIM + c) = o;
}

// ---------------- host orchestration ----------------------------------------
extern "C" void kernel_launch(void* const* d_in, const int* in_sizes, int n_in,
                              void* d_out, int out_size) {
    const float* x       = (const float*)d_in[0];
    const void* ei       = d_in[1];
    const float* w0      = (const float*)d_in[2];
    const float* b0      = (const float*)d_in[3];
    const float* asrc0   = (const float*)d_in[4];
    const float* adst0   = (const float*)d_in[5];
    const float* res_w0  = (const float*)d_in[6];
    const float* w1      = (const float*)d_in[7];
    const float* b1      = (const float*)d_in[8];
    const float* asrc1   = (const float*)d_in[9];
    const float* adst1   = (const float*)d_in[10];
    const float* w2      = (const float*)d_in[11];
    const float* b2      = (const float*)d_in[12];
    const float* asrc2   = (const float*)d_in[13];
    const float* adst2   = (const float*)d_in[14];
    float* out           = (float*)d_out;

    int E = in_sizes[1] / 2;

    // lazy one-time stream/event creation (host resources only, no device mem)
    static cudaStream_t s2 = nullptr;
    static cudaEvent_t evFork = nullptr, evJoin = nullptr;
    if (s2 == nullptr) {
        cudaStreamCreateWithFlags(&s2, cudaStreamNonBlocking);
        cudaEventCreateWithFlags(&evFork, cudaEventDisableTiming);
        cudaEventCreateWithFlags(&evJoin, cudaEventDisableTiming);
    }

    // fork: CSR build on s2, overlapped with layer-0 GEMMs on main stream
    cudaEventRecord(evFork, 0);
    cudaStreamWaitEvent(s2, evFork, 0);
    detect_k<<<1, 1, 0, s2>>>(ei);
    init_deg_k<<<(NN + 255) / 256, 256, 0, s2>>>();
    hist_k<<<(E + 255) / 256, 256, 0, s2>>>(ei, E);
    scan_k<<<1, 1024, 0, s2>>>();
    scatter_k<<<(E + NN + 255) / 256, 256, 0, s2>>>(ei, E);
    cudaEventRecord(evJoin, s2);

    dim3 ggrid(FDIM / GBN, (NN + GBM - 1) / GBM);

    // selectors: 0 = external ptr, 1 = sc_a, 2 = sc_b, 3 = sc_g
    tgemm_k<<<ggrid, 256>>>(x, 0, w0, 3, NN, 256);
    tgemm_k<<<ggrid, 256>>>(x, 0, res_w0, 2, NN, 256);
    scores_k<<<NN, 128>>>(asrc0, adst0);

    cudaStreamWaitEvent(0, evJoin, 0);     // CSR ready before first agg
    agg_k<<<NN, 128>>>(b0, /*res=*/2, nullptr, /*out=*/1);   // h1 -> sc_a

    tgemm_k<<<ggrid, 256>>>(nullptr, 1, w1, 3, NN, 512);
    scores_k<<<NN, 128>>>(asrc1, adst1);
    agg_k<<<NN, 128>>>(b1, /*res=*/1, nullptr, /*out=*/2);   // h2 -> sc_b

    tgemm_k<<<ggrid, 256>>>(nullptr, 2, w2, 3, NN, 512);
    scores_k<<<NN, 128>>>(asrc2, adst2);
    agg_k<<<NN, 128>>>(b2, /*res=*/2, out, /*out=*/0);
}

// round 8
// speedup vs baseline: 2.5402x; 1.1436x over previous
#include <cuda_runtime.h>
#include <cuda_fp16.h>
#include <math.h>

#define NN   20000
#define EMAX 320000
#define FDIM 512
#define NH   4
#define HC   128
#define DCAP 256

// ---------------- scratch (static device globals; no allocation) ------------
__device__ __half sc_gh[(size_t)NN * FDIM]; // projected features g (fp16)
__device__ float  sc_a[(size_t)NN * FDIM];  // ping buffer (h1)
__device__ float  sc_b[(size_t)NN * FDIM];  // pong buffer (res0 / h2)
__device__ float  sc_es[NN * NH];
__device__ float  sc_ed[NN * NH];
__device__ int    sc_deg[NN];
__device__ int    sc_rowptr[NN + 1];
__device__ int    sc_cursor[NN];
__device__ int    sc_csr[EMAX + NN];
__device__ int    sc_is64;                  // 1 if edge_index is int64

__device__ __forceinline__ float* pick_rw(int sel, float* ext) {
    if (sel == 0) return ext;
    if (sel == 1) return sc_a;
    return sc_b;
}
__device__ __forceinline__ const float* pick_ro(int sel, const float* ext) {
    if (sel == 0) return ext;
    if (sel == 1) return sc_a;
    return sc_b;
}

__device__ __forceinline__ int load_edge(const void* ei, size_t idx) {
    if (sc_is64) return (int)((const long long*)ei)[idx];
    return ((const int*)ei)[idx];
}

// ---------------- dtype probe ------------------------------------------------
__global__ void detect_k(const void* ei) {
    const int* p = (const int*)ei;
    int any = 0;
#pragma unroll 8
    for (int i = 0; i < 256; i++) any |= p[2 * i + 1];
    sc_is64 = (any == 0) ? 1 : 0;
}

// ---------------- CSR build -------------------------------------------------
__global__ void init_deg_k() {
    int i = blockIdx.x * blockDim.x + threadIdx.x;
    if (i < NN) sc_deg[i] = 1;   // self loop
}

__global__ void hist_k(const void* ei, int E) {
    int e = blockIdx.x * blockDim.x + threadIdx.x;
    if (e < E) {
        int d = load_edge(ei, (size_t)E + e);
        atomicAdd(&sc_deg[d], 1);
    }
}

__global__ void scan_k() {
    __shared__ int sums[1024];
    const int CH = 20;
    int t = threadIdx.x;
    int base = t * CH;
    int local[CH];
    int s = 0;
#pragma unroll
    for (int i = 0; i < CH; i++) {
        int idx = base + i;
        int v = (idx < NN) ? sc_deg[idx] : 0;
        local[i] = s;
        s += v;
    }
    sums[t] = s;
    __syncthreads();
    for (int off = 1; off < 1024; off <<= 1) {
        int v = (t >= off) ? sums[t - off] : 0;
        __syncthreads();
        sums[t] += v;
        __syncthreads();
    }
    int offset = (t == 0) ? 0 : sums[t - 1];
#pragma unroll
    for (int i = 0; i < CH; i++) {
        int idx = base + i;
        if (idx < NN) {
            int r = offset + local[i];
            sc_rowptr[idx] = r;
            sc_cursor[idx] = r;
        }
    }
    if (t == 1023) sc_rowptr[NN] = sums[1023];
}

__global__ void scatter_k(const void* ei, int E) {
    int i = blockIdx.x * blockDim.x + threadIdx.x;
    if (i < E) {
        int d = load_edge(ei, (size_t)E + i);
        int s = load_edge(ei, i);
        int slot = atomicAdd(&sc_cursor[d], 1);
        sc_csr[slot] = s;
    } else if (i < E + NN) {
        int v = i - E;
        int slot = atomicAdd(&sc_cursor[v], 1);
        sc_csr[slot] = v;
    }
}

// ---------------- TF32 tensor-core GEMM + fused score / fp16-g epilogue -----
#define GBM 128
#define GBN 128
#define GBK 32
#define AS_LD 36
#define BS_LD 136

__device__ __forceinline__ float to_tf32(float x) {
    unsigned y;
    asm("cvt.rna.tf32.f32 %0, %1;" : "=r"(y) : "f"(x));
    return __uint_as_float(y);
}

__device__ __forceinline__ void mma_tf32(float* d, const float* a, const float* b) {
    unsigned const* A = (unsigned const*)a;
    unsigned const* B = (unsigned const*)b;
    asm volatile(
        "mma.sync.aligned.m16n8k8.row.col.f32.tf32.tf32.f32 "
        "{%0,%1,%2,%3}, {%4,%5,%6,%7}, {%8,%9}, {%0,%1,%2,%3};"
        : "+f"(d[0]), "+f"(d[1]), "+f"(d[2]), "+f"(d[3])
        : "r"(A[0]), "r"(A[1]), "r"(A[2]), "r"(A[3]), "r"(B[0]), "r"(B[1]));
}

// mode 0: C (fp32, via csel) = A@B            (residual GEMM)
// mode 1: sc_gh (fp16) = A@B, and sc_es/sc_ed computed from fp32 accumulators
__global__ __launch_bounds__(256, 1) void tgemm_k(const float* __restrict__ Aext,
                                                  int asel,
                                                  const float* __restrict__ B,
                                                  int csel, int mode,
                                                  const float* __restrict__ avS,
                                                  const float* __restrict__ avD,
                                                  int M, int K) {
    const float* A = pick_ro(asel, Aext);

    __shared__ float As[GBM][AS_LD];
    __shared__ float Bs[GBK][BS_LD];
    __shared__ float es_sh[GBM];
    __shared__ float ed_sh[GBM];

    int tid  = threadIdx.x;
    int lane = tid & 31;
    int warp = tid >> 5;
    int wm = (warp >> 2) * 64;
    int wn = (warp & 3) * 32;
    int bm = blockIdx.y * GBM;
    int bn = blockIdx.x * GBN;

    if (mode && tid < GBM) { es_sh[tid] = 0.f; ed_sh[tid] = 0.f; }

    int aRow = tid >> 3;
    int aCol = (tid & 7) * 4;
    int bRow = tid >> 5;
    int bCol = (tid & 31) * 4;

    float acc[4][4][4];
#pragma unroll
    for (int i = 0; i < 4; i++)
#pragma unroll
        for (int j = 0; j < 4; j++)
#pragma unroll
            for (int q = 0; q < 4; q++) acc[i][j][q] = 0.f;

    float4 ra[4], rb[4];
    int nk = K / GBK;

#pragma unroll
    for (int i = 0; i < 4; i++) {
        int r = aRow + 32 * i;
        ra[i] = (bm + r < M) ? *(const float4*)(A + (size_t)(bm + r) * K + aCol)
                             : make_float4(0.f, 0.f, 0.f, 0.f);
        rb[i] = *(const float4*)(B + (size_t)(bRow + 8 * i) * FDIM + bn + bCol);
    }

    for (int kt = 0; kt < nk; kt++) {
#pragma unroll
        for (int i = 0; i < 4; i++) {
            int m = aRow + 32 * i;
            As[m][aCol + 0] = to_tf32(ra[i].x);
            As[m][aCol + 1] = to_tf32(ra[i].y);
            As[m][aCol + 2] = to_tf32(ra[i].z);
            As[m][aCol + 3] = to_tf32(ra[i].w);
            float4 v = rb[i];
            v.x = to_tf32(v.x); v.y = to_tf32(v.y);
            v.z = to_tf32(v.z); v.w = to_tf32(v.w);
            *(float4*)&Bs[bRow + 8 * i][bCol] = v;
        }
        __syncthreads();

        if (kt + 1 < nk) {
            int kb = (kt + 1) * GBK;
#pragma unroll
            for (int i = 0; i < 4; i++) {
                int r = aRow + 32 * i;
                ra[i] = (bm + r < M)
                      ? *(const float4*)(A + (size_t)(bm + r) * K + kb + aCol)
                      : make_float4(0.f, 0.f, 0.f, 0.f);
                rb[i] = *(const float4*)(B + (size_t)(kb + bRow + 8 * i) * FDIM + bn + bCol);
            }
        }

#pragma unroll
        for (int ks = 0; ks < 4; ks++) {
            int k0 = ks * 8;
            float afr[4][4], bfr[4][2];
#pragma unroll
            for (int mt = 0; mt < 4; mt++) {
                int m = wm + mt * 16 + (lane >> 2);
                int k = k0 + (lane & 3);
                afr[mt][0] = As[m][k];
                afr[mt][1] = As[m + 8][k];
                afr[mt][2] = As[m][k + 4];
                afr[mt][3] = As[m + 8][k + 4];
            }
#pragma unroll
            for (int nt = 0; nt < 4; nt++) {
                int n = wn + nt * 8 + (lane >> 2);
                int k = k0 + (lane & 3);
                bfr[nt][0] = Bs[k][n];
                bfr[nt][1] = Bs[k + 4][n];
            }
#pragma unroll
            for (int mt = 0; mt < 4; mt++)
#pragma unroll
                for (int nt = 0; nt < 4; nt++)
                    mma_tf32(acc[mt][nt], afr[mt], bfr[nt]);
        }
        __syncthreads();
    }

    if (mode == 0) {
        float* C = pick_rw(csel, nullptr);
#pragma unroll
        for (int mt = 0; mt < 4; mt++) {
#pragma unroll
            for (int nt = 0; nt < 4; nt++) {
                int r = bm + wm + mt * 16 + (lane >> 2);
                int c = bn + wn + nt * 8 + (lane & 3) * 2;
                if (r < M)
                    *(float2*)(C + (size_t)r * FDIM + c) =
                        make_float2(acc[mt][nt][0], acc[mt][nt][1]);
                if (r + 8 < M)
                    *(float2*)(C + (size_t)(r + 8) * FDIM + c) =
                        make_float2(acc[mt][nt][2], acc[mt][nt][3]);
            }
        }
    } else {
        // fp16 g store + fused per-head scores (this block IS one head: bn = head*HC)
        float asv[8], adv[8];
#pragma unroll
        for (int nt = 0; nt < 4; nt++)
#pragma unroll
            for (int p = 0; p < 2; p++) {
                int c = bn + wn + nt * 8 + (lane & 3) * 2 + p;
                asv[nt * 2 + p] = avS[c];
                adv[nt * 2 + p] = avD[c];
            }

        float s1[8], s2[8];
#pragma unroll
        for (int i = 0; i < 8; i++) { s1[i] = 0.f; s2[i] = 0.f; }

#pragma unroll
        for (int mt = 0; mt < 4; mt++) {
#pragma unroll
            for (int nt = 0; nt < 4; nt++) {
                int r = bm + wm + mt * 16 + (lane >> 2);
                int c = bn + wn + nt * 8 + (lane & 3) * 2;
                if (r < M)
                    *(__half2*)(sc_gh + (size_t)r * FDIM + c) =
                        __floats2half2_rn(acc[mt][nt][0], acc[mt][nt][1]);
                if (r + 8 < M)
                    *(__half2*)(sc_gh + (size_t)(r + 8) * FDIM + c) =
                        __floats2half2_rn(acc[mt][nt][2], acc[mt][nt][3]);
#pragma unroll
                for (int q = 0; q < 4; q++) {
                    int qh = q >> 1, p = q & 1;
                    s1[mt * 2 + qh] += acc[mt][nt][q] * asv[nt * 2 + p];
                    s2[mt * 2 + qh] += acc[mt][nt][q] * adv[nt * 2 + p];
                }
            }
        }
        // reduce over the 4-thread quad (lane&3) that shares rows
#pragma unroll
        for (int off = 1; off <= 2; off <<= 1)
#pragma unroll
            for (int i = 0; i < 8; i++) {
                s1[i] += __shfl_xor_sync(0xffffffffu, s1[i], off);
                s2[i] += __shfl_xor_sync(0xffffffffu, s2[i], off);
            }
        if ((lane & 3) == 0) {
#pragma unroll
            for (int mt = 0; mt < 4; mt++)
#pragma unroll
                for (int qh = 0; qh < 2; qh++) {
                    int rl = wm + mt * 16 + (lane >> 2) + 8 * qh;
                    atomicAdd(&es_sh[rl], s1[mt * 2 + qh]);
                    atomicAdd(&ed_sh[rl], s2[mt * 2 + qh]);
                }
        }
        __syncthreads();
        if (tid < GBM) {
            int r = bm + tid;
            if (r < M) {
                sc_es[r * NH + blockIdx.x] = es_sh[tid];
                sc_ed[r * NH + blockIdx.x] = ed_sh[tid];
            }
        }
    }
}

// ---------------- fused segment softmax + aggregate + bias + res + relu -----
__global__ __launch_bounds__(128) void agg_k(const float* __restrict__ bias,
                                             int rsel,
                                             float* __restrict__ outext,
                                             int osel) {
    const float* res = pick_ro(rsel, nullptr);
    float* out = pick_rw(osel, outext);

    __shared__ float w_sh[NH][DCAP];
    __shared__ int   idx_sh[DCAP];

    int d = blockIdx.x;
    int w = threadIdx.x >> 5, lane = threadIdx.x & 31;
    int beg = sc_rowptr[d], end = sc_rowptr[d + 1];
    int deg = end - beg;
    float edv = sc_ed[d * NH + w];

    float4 acc = make_float4(0.f, 0.f, 0.f, 0.f);
    const __half* ghp = sc_gh + w * HC + 4 * lane;

    if (deg <= DCAP) {
        float m = -INFINITY;
        for (int j = lane; j < deg; j += 32) {
            int s = sc_csr[beg + j];
            if (w == 0) idx_sh[j] = s;
            float e = sc_es[s * NH + w] + edv;
            e = e > 0.f ? e : 0.2f * e;
            w_sh[w][j] = e;
            m = fmaxf(m, e);
        }
#pragma unroll
        for (int o = 16; o; o >>= 1) m = fmaxf(m, __shfl_xor_sync(0xffffffffu, m, o));

        float den = 0.f;
        for (int j = lane; j < deg; j += 32) {
            float ex = __expf(w_sh[w][j] - m);
            w_sh[w][j] = ex;
            den += ex;
        }
#pragma unroll
        for (int o = 16; o; o >>= 1) den += __shfl_xor_sync(0xffffffffu, den, o);
        float inv = 1.f / (den + 1e-16f);

        __syncthreads();

#pragma unroll 4
        for (int j = 0; j < deg; j++) {
            int s = idx_sh[j];
            float wt = w_sh[w][j] * inv;
            uint2 hv = *(const uint2*)(ghp + (size_t)s * FDIM);
            float2 f0 = __half22float2(*(const __half2*)&hv.x);
            float2 f1 = __half22float2(*(const __half2*)&hv.y);
            acc.x += wt * f0.x;
            acc.y += wt * f0.y;
            acc.z += wt * f1.x;
            acc.w += wt * f1.y;
        }
    } else {
        float m = -INFINITY;
        for (int j = beg + lane; j < end; j += 32) {
            int s = sc_csr[j];
            float e = sc_es[s * NH + w] + edv;
            e = e > 0.f ? e : 0.2f * e;
            m = fmaxf(m, e);
        }
#pragma unroll
        for (int o = 16; o; o >>= 1) m = fmaxf(m, __shfl_xor_sync(0xffffffffu, m, o));
        float den = 0.f;
        for (int j = beg + lane; j < end; j += 32) {
            int s = sc_csr[j];
            float e = sc_es[s * NH + w] + edv;
            e = e > 0.f ? e : 0.2f * e;
            den += __expf(e - m);
        }
#pragma unroll
        for (int o = 16; o; o >>= 1) den += __shfl_xor_sync(0xffffffffu, den, o);
        float inv = 1.f / (den + 1e-16f);
#pragma unroll 4
        for (int j = beg; j < end; j++) {
            int s = sc_csr[j];
            float e = sc_es[s * NH + w] + edv;
            e = e > 0.f ? e : 0.2f * e;
            float wt = __expf(e - m) * inv;
            uint2 hv = *(const uint2*)(ghp + (size_t)s * FDIM);
            float2 f0 = __half22float2(*(const __half2*)&hv.x);
            float2 f1 = __half22float2(*(const __half2*)&hv.y);
            acc.x += wt * f0.x;
            acc.y += wt * f0.y;
            acc.z += wt * f1.x;
            acc.w += wt * f1.y;
        }
    }

    int c = w * HC + 4 * lane;
    float4 bv = *(const float4*)(bias + c);
    float4 rv = *(const float4*)(res + (size_t)d * FDIM + c);
    float4 o;
    o.x = fmaxf(acc.x + bv.x + rv.x, 0.f);
    o.y = fmaxf(acc.y + bv.y + rv.y, 0.f);
    o.z = fmaxf(acc.z + bv.z + rv.z, 0.f);
    o.w = fmaxf(acc.w + bv.w + rv.w, 0.f);
    *(float4*)(out + (size_t)d * FDIM + c) = o;
}

// ---------------- host orchestration ----------------------------------------
extern "C" void kernel_launch(void* const* d_in, const int* in_sizes, int n_in,
                              void* d_out, int out_size) {
    const float* x       = (const float*)d_in[0];
    const void* ei       = d_in[1];
    const float* w0      = (const float*)d_in[2];
    const float* b0      = (const float*)d_in[3];
    const float* asrc0   = (const float*)d_in[4];
    const float* adst0   = (const float*)d_in[5];
    const float* res_w0  = (const float*)d_in[6];
    const float* w1      = (const float*)d_in[7];
    const float* b1      = (const float*)d_in[8];
    const float* asrc1   = (const float*)d_in[9];
    const float* adst1   = (const float*)d_in[10];
    const float* w2      = (const float*)d_in[11];
    const float* b2      = (const float*)d_in[12];
    const float* asrc2   = (const float*)d_in[13];
    const float* adst2   = (const float*)d_in[14];
    float* out           = (float*)d_out;

    int E = in_sizes[1] / 2;

    static cudaStream_t s2 = nullptr;
    static cudaEvent_t evFork = nullptr, evJoin = nullptr;
    if (s2 == nullptr) {
        cudaStreamCreateWithFlags(&s2, cudaStreamNonBlocking);
        cudaEventCreateWithFlags(&evFork, cudaEventDisableTiming);
        cudaEventCreateWithFlags(&evJoin, cudaEventDisableTiming);
    }

    cudaEventRecord(evFork, 0);
    cudaStreamWaitEvent(s2, evFork, 0);
    detect_k<<<1, 1, 0, s2>>>(ei);
    init_deg_k<<<(NN + 255) / 256, 256, 0, s2>>>();
    hist_k<<<(E + 255) / 256, 256, 0, s2>>>(ei, E);
    scan_k<<<1, 1024, 0, s2>>>();
    scatter_k<<<(E + NN + 255) / 256, 256, 0, s2>>>(ei, E);
    cudaEventRecord(evJoin, s2);

    dim3 ggrid(FDIM / GBN, (NN + GBM - 1) / GBM);

    // buffer selectors: 0 = external ptr, 1 = sc_a, 2 = sc_b
    // layer 0: proj (fp16 g + scores) ; residual fp32 -> sc_b
    tgemm_k<<<ggrid, 256>>>(x, 0, w0, 0, 1, asrc0, adst0, NN, 256);
    tgemm_k<<<ggrid, 256>>>(x, 0, res_w0, 2, 0, nullptr, nullptr, NN, 256);

    cudaStreamWaitEvent(0, evJoin, 0);
    agg_k<<<NN, 128>>>(b0, /*res=*/2, nullptr, /*out=*/1);   // h1 -> sc_a

    tgemm_k<<<ggrid, 256>>>(nullptr, 1, w1, 0, 1, asrc1, adst1, NN, 512);
    agg_k<<<NN, 128>>>(b1, /*res=*/1, nullptr, /*out=*/2);   // h2 -> sc_b

    tgemm_k<<<ggrid, 256>>>(nullptr, 2, w2, 0, 1, asrc2, adst2, NN, 512);
    agg_k<<<NN, 128>>>(b2, /*res=*/2, out, /*out=*/0);
}